// round 4
// baseline (speedup 1.0000x reference)
#include <cuda_runtime.h>
#include <cstdint>

// ---------------------------------------------------------------------------
// LocationSlayerArch, round 4: fully fused layer-1 (sparse gemm + recurrence
// + sparse L2 partial) in one kernel; pre-activations never touch HBM.
//   k_bitify : active-input index lists (premultiplied byte offsets)
//   k_fused  : per (hb,n,path): chunked [gemm -> recurrence] + L2 partial
//   k_final  : hb-reduction + layer-2 recurrence + output
// ---------------------------------------------------------------------------

#define N_BATCH 128
#define T_SEQ   156
#define C_IN    156
#define H_DIM   1024
#define O_DIM   20
#define HB_CNT  8
#define HB_SZ   128
#define IDX_CAP 160
#define CHUNK   39                    // 156 = 4 * 39
#define ROW_BYTES 512                 // ws row stride (128 floats)

#define LAM_S  0.90483741803595952f
#define K_PSP  0.27182818284590452f
#define LAM_R  0.36787944117144233f
#define C_REF  -54.365636569180902f
#define C_P16  1.1253517471925912e-07f
#define C_Q16  1.8005627955081459e-06f
#define THETA  10.0f

__device__ __constant__ int c_td[39] = {
    11,25,35,4,18,30,7,2,20,37,29,12,9,33,23,16,1,6,15,21,
    27,34,39,24,17,10,31,38,28,14,3,22,32,8,19,36,5,13,26};

__device__ unsigned g_idx[(size_t)2 * N_BATCH * T_SEQ * IDX_CAP];
__device__ int      g_cnt[2 * N_BATCH * T_SEQ];
__device__ float    g_v2part[(size_t)2 * HB_CNT * N_BATCH * T_SEQ * O_DIM]; // 51MB

// ---------------------------------------------------------------------------
// K0: build active-index lists. grid (n, path), 160 threads.
// ---------------------------------------------------------------------------
__global__ void __launch_bounds__(160) k_bitify(const float* __restrict__ x) {
    extern __shared__ float xs[];                 // [C_IN][T_SEQ]
    int n = blockIdx.x, path = blockIdx.y;
    const float* xb = x + (size_t)n * C_IN * T_SEQ;
    for (int i = threadIdx.x; i < C_IN * T_SEQ; i += blockDim.x) xs[i] = xb[i];
    __syncthreads();

    int seq = threadIdx.x;
    if (seq >= T_SEQ) return;
    unsigned* ob = g_idx + ((size_t)(path * N_BATCH + n) * T_SEQ + seq) * IDX_CAP;
    int cnt = 0;
    if (path == 0) {
        int t = seq;
        for (int c = 0; c < C_IN; c++)
            if (xs[c * T_SEQ + t] > 0.5f) ob[cnt++] = (unsigned)(c * ROW_BYTES);
    } else {
        int cp = seq;
        int blk = cp / 78, j2 = cp % 78;
        int pc = 2 * c_td[j2 >> 1] - 2 + (j2 & 1) + blk * 78;   // PERM[cp]
        for (int t = 0; t < T_SEQ; t++)
            if (xs[pc * T_SEQ + t] > 0.5f) ob[cnt++] = (unsigned)(t * ROW_BYTES);
    }
    while (cnt & 3) ob[cnt++] = (unsigned)(C_IN * ROW_BYTES);  // dummy zero row
    g_cnt[(path * N_BATCH + n) * T_SEQ + seq] = cnt;
}

// ---------------------------------------------------------------------------
// K1: fused layer 1. grid (hb, n, path), 256 threads.
//   smem: ws [157][128] weights (row 156 = zeros), w2s [128][20],
//         pre [39][128] chunk pre-activations, sb [156][4] spike bitmasks.
//   Phase A (8 warps): sparse matvec -> pre.   Phase B (128 thr): recurrence.
//   Phase C: sparse L2 partial -> g_v2part.
// ---------------------------------------------------------------------------
#define SM_WS   (157 * 128)
#define SM_W2S  (HB_SZ * O_DIM)
#define SM_PRE  (CHUNK * HB_SZ)
#define SM_FLT  (SM_WS + SM_W2S + SM_PRE)
#define SM1_BYTES ((SM_FLT + T_SEQ * 4) * 4)

__global__ void __launch_bounds__(256) k_fused(const float* __restrict__ w_main,
                                               const float* __restrict__ w_loc,
                                               const float* __restrict__ wb_main,
                                               const float* __restrict__ wb_loc) {
    extern __shared__ float smem[];
    float* ws  = smem;                 // [157][128]
    float* w2s = smem + SM_WS;         // [128][20]
    float* pre = w2s + SM_W2S;         // [CHUNK][128]
    unsigned* sb = (unsigned*)(pre + SM_PRE);   // [156][4]

    int hb = blockIdx.x, n = blockIdx.y, path = blockIdx.z;
    int tid = threadIdx.x;
    int wrp = tid >> 5, lane = tid & 31;
    const float* wa = path ? w_loc : w_main;
    const float* wb = path ? wb_loc : wb_main;

    // load weight tiles
    for (int i = tid; i < HB_SZ * C_IN; i += 256) {
        int hl = i / C_IN, c = i % C_IN;
        ws[c * HB_SZ + hl] = wa[(size_t)(hb * HB_SZ + hl) * C_IN + c];
    }
    for (int i = tid; i < HB_SZ; i += 256) ws[C_IN * HB_SZ + i] = 0.0f;
    for (int i = tid; i < O_DIM * HB_SZ; i += 256) {
        int h = i % HB_SZ, o = i / HB_SZ;
        w2s[h * O_DIM + o] = wb[(size_t)o * H_DIM + hb * HB_SZ + h];
    }
    __syncthreads();

    uint32_t ws32;
    asm("{ .reg .u64 t; cvta.to.shared.u64 t, %1; cvt.u32.u64 %0, t; }"
        : "=r"(ws32) : "l"(ws));
    uint32_t base = ws32 + lane * 16;

    const int seqbase = (path * N_BATCH + n) * T_SEQ;

    // recurrence state (threads 0..127; one hidden unit each)
    float A = 0.f, B = 0.f, P = 0.f, Q = 0.f;
    unsigned hist = 0u;

    for (int t0 = 0; t0 < T_SEQ; t0 += CHUNK) {
        // ---- Phase A: sparse gemm for t in [t0, t0+CHUNK) ----
        for (int t = t0 + wrp; t < t0 + CHUNK; t += 8) {
            const unsigned* ib = g_idx + (size_t)(seqbase + t) * IDX_CAP;
            int cnt = g_cnt[seqbase + t];
            unsigned long long acc0 = 0ULL, acc1 = 0ULL;
            for (int k = 0; k < cnt; k += 4) {
                uint4 v = *(const uint4*)(ib + k);
                unsigned long long a, b;
                asm volatile("ld.shared.v2.b64 {%0,%1}, [%2];" : "=l"(a), "=l"(b) : "r"(base + v.x));
                asm("add.rn.f32x2 %0, %0, %1;" : "+l"(acc0) : "l"(a));
                asm("add.rn.f32x2 %0, %0, %1;" : "+l"(acc1) : "l"(b));
                asm volatile("ld.shared.v2.b64 {%0,%1}, [%2];" : "=l"(a), "=l"(b) : "r"(base + v.y));
                asm("add.rn.f32x2 %0, %0, %1;" : "+l"(acc0) : "l"(a));
                asm("add.rn.f32x2 %0, %0, %1;" : "+l"(acc1) : "l"(b));
                asm volatile("ld.shared.v2.b64 {%0,%1}, [%2];" : "=l"(a), "=l"(b) : "r"(base + v.z));
                asm("add.rn.f32x2 %0, %0, %1;" : "+l"(acc0) : "l"(a));
                asm("add.rn.f32x2 %0, %0, %1;" : "+l"(acc1) : "l"(b));
                asm volatile("ld.shared.v2.b64 {%0,%1}, [%2];" : "=l"(a), "=l"(b) : "r"(base + v.w));
                asm("add.rn.f32x2 %0, %0, %1;" : "+l"(acc0) : "l"(a));
                asm("add.rn.f32x2 %0, %0, %1;" : "+l"(acc1) : "l"(b));
            }
            uint2 u0 = *reinterpret_cast<uint2*>(&acc0);
            uint2 u1 = *reinterpret_cast<uint2*>(&acc1);
            float4 r;
            r.x = __uint_as_float(u0.x); r.y = __uint_as_float(u0.y);
            r.z = __uint_as_float(u1.x); r.w = __uint_as_float(u1.y);
            *(float4*)(pre + (t - t0) * HB_SZ + lane * 4) = r;
        }
        __syncthreads();

        // ---- Phase B: recurrence over this chunk (threads 0..127) ----
        if (tid < HB_SZ) {
            #pragma unroll 3
            for (int tl = 0; tl < CHUNK; tl++) {
                float acc = pre[tl * HB_SZ + tid];
                B = LAM_S * (B + A);
                A = LAM_S * A + acc;
                float u  = K_PSP * B;
                float um = u + C_REF * Q;
                unsigned spk = (um >= THETA) ? 1u : 0u;
                float s = (float)spk;
                float aged = (float)((hist >> 14) & 1u);
                Q = LAM_R * (Q + P + s) - aged * C_Q16;
                P = LAM_R * (P + s)     - aged * C_P16;
                hist = (hist << 1) | spk;
                unsigned bal = __ballot_sync(0xffffffffu, spk);
                if (lane == 0) sb[(t0 + tl) * 4 + wrp] = bal;
            }
        }
        __syncthreads();
    }

    // ---- Phase C: sparse L2 partial over set bits ----
    float* vout = g_v2part + (size_t)((path * HB_CNT + hb) * N_BATCH + n) * (T_SEQ * O_DIM);
    for (int task = tid; task < T_SEQ * O_DIM; task += 256) {
        int t = task / O_DIM, o = task % O_DIM;
        float acc = 0.f;
        #pragma unroll
        for (int wd = 0; wd < 4; wd++) {
            unsigned m = sb[t * 4 + wd];
            const float* wcol = w2s + wd * 32 * O_DIM + o;
            while (m) {
                int j = __ffs(m) - 1;
                m &= m - 1u;
                acc += wcol[j * O_DIM];
            }
        }
        vout[task] = acc;
    }
}

// ---------------------------------------------------------------------------
// K2: sum 8 h-block partials into smem, then layer-2 recurrence + output.
// grid 256 = (path, n), 128 threads.
// ---------------------------------------------------------------------------
#define TO (T_SEQ * O_DIM)   // 3120
__global__ void __launch_bounds__(128) k_final(float* __restrict__ out) {
    __shared__ float v[TO];
    int b = blockIdx.x;
    int path = b >> 7, n = b & 127;
    int tid = threadIdx.x;

    const float* basep = g_v2part + (size_t)(path * HB_CNT * N_BATCH + n) * TO;
    for (int i = tid; i < TO; i += 128) {
        float acc = 0.f;
        #pragma unroll
        for (int hb = 0; hb < HB_CNT; hb++)
            acc += basep[(size_t)hb * N_BATCH * TO + i];
        v[i] = acc;
    }
    __syncthreads();

    if (tid < O_DIM) {
        int o = tid;
        float* op = out + ((size_t)n * O_DIM + o) * 312 + path * T_SEQ;
        float A = 0.f, B = 0.f, P = 0.f, Q = 0.f;
        unsigned hist = 0u;
        #pragma unroll 4
        for (int t = 0; t < T_SEQ; t++) {
            float pre = v[t * O_DIM + o];
            B = LAM_S * (B + A);
            A = LAM_S * A + pre;
            float u  = K_PSP * B;
            float um = u + C_REF * Q;
            unsigned spk = (um >= THETA) ? 1u : 0u;
            float s = (float)spk;
            float aged = (float)((hist >> 14) & 1u);
            Q = LAM_R * (Q + P + s) - aged * C_Q16;
            P = LAM_R * (P + s)     - aged * C_P16;
            hist = (hist << 1) | spk;
            op[t] = s;
        }
    }
}

// ---------------------------------------------------------------------------
extern "C" void kernel_launch(void* const* d_in, const int* in_sizes, int n_in,
                              void* d_out, int out_size) {
    const float* x   = (const float*)d_in[0];
    const float* w1  = (const float*)d_in[1];
    const float* w2  = (const float*)d_in[2];
    const float* wl1 = (const float*)d_in[3];
    const float* wl2 = (const float*)d_in[4];
    float* out = (float*)d_out;

    const int SM0 = C_IN * T_SEQ * 4;                 // 97344
    cudaFuncSetAttribute(k_bitify, cudaFuncAttributeMaxDynamicSharedMemorySize, SM0);
    cudaFuncSetAttribute(k_fused,  cudaFuncAttributeMaxDynamicSharedMemorySize, SM1_BYTES);

    dim3 g0(N_BATCH, 2);
    k_bitify<<<g0, 160, SM0>>>(x);

    dim3 g1(HB_CNT, N_BATCH, 2);
    k_fused<<<g1, 256, SM1_BYTES>>>(w1, wl1, w2, wl2);

    k_final<<<2 * N_BATCH, 128>>>(out);
}

// round 5
// speedup vs baseline: 1.2497x; 1.2497x over previous
#include <cuda_runtime.h>
#include <cstdint>

// ---------------------------------------------------------------------------
// LocationSlayerArch, round 5: back to split pipeline (round-3 structure),
// with 512-thread gemm (2x occupancy), per-t vectorized L2 partial, and
// both-paths bitify.
//   k_bitify : active-input index lists (premultiplied byte offsets)
//   k_gemm1  : sparse layer-1 GEMM -> g_pre
//   k_neuron1: psp+spike recurrence + vectorized sparse L2 partial
//   k_final  : hb-reduction + layer-2 recurrence + output
// ---------------------------------------------------------------------------

#define N_BATCH 128
#define T_SEQ   156
#define C_IN    156
#define H_DIM   1024
#define O_DIM   20
#define HB_CNT  8
#define HB_SZ   128
#define IDX_CAP 160
#define ROW_BYTES 512                 // ws row stride (128 floats)

#define LAM_S  0.90483741803595952f
#define K_PSP  0.27182818284590452f
#define LAM_R  0.36787944117144233f
#define C_REF  -54.365636569180902f
#define C_P16  1.1253517471925912e-07f
#define C_Q16  1.8005627955081459e-06f
#define THETA  10.0f

__device__ __constant__ int c_td[39] = {
    11,25,35,4,18,30,7,2,20,37,29,12,9,33,23,16,1,6,15,21,
    27,34,39,24,17,10,31,38,28,14,3,22,32,8,19,36,5,13,26};

__device__ unsigned g_idx[(size_t)2 * N_BATCH * T_SEQ * IDX_CAP];
__device__ int      g_cnt[2 * N_BATCH * T_SEQ];
__device__ float    g_pre[(size_t)2 * N_BATCH * HB_CNT * T_SEQ * HB_SZ];    // 163MB
__device__ float    g_v2part[(size_t)2 * HB_CNT * N_BATCH * T_SEQ * O_DIM]; // 51MB

// ---------------------------------------------------------------------------
// K0: build active-index lists for BOTH paths. grid n, 320 threads.
// ---------------------------------------------------------------------------
__global__ void __launch_bounds__(320) k_bitify(const float* __restrict__ x) {
    extern __shared__ float xs[];                 // [C_IN][T_SEQ]
    int n = blockIdx.x;
    const float* xb = x + (size_t)n * C_IN * T_SEQ;
    for (int i = threadIdx.x; i < C_IN * T_SEQ; i += blockDim.x) xs[i] = xb[i];
    __syncthreads();

    int task = threadIdx.x;
    if (task >= 2 * T_SEQ) return;
    int path = task >= T_SEQ;
    int seq = path ? task - T_SEQ : task;
    unsigned* ob = g_idx + ((size_t)(path * N_BATCH + n) * T_SEQ + seq) * IDX_CAP;
    int cnt = 0;
    if (path == 0) {
        int t = seq;
        for (int c = 0; c < C_IN; c++)
            if (xs[c * T_SEQ + t] > 0.5f) ob[cnt++] = (unsigned)(c * ROW_BYTES);
    } else {
        int cp = seq;
        int blk = cp / 78, j2 = cp % 78;
        int pc = 2 * c_td[j2 >> 1] - 2 + (j2 & 1) + blk * 78;   // PERM[cp]
        for (int t = 0; t < T_SEQ; t++)
            if (xs[pc * T_SEQ + t] > 0.5f) ob[cnt++] = (unsigned)(t * ROW_BYTES);
    }
    while (cnt & 3) ob[cnt++] = (unsigned)(C_IN * ROW_BYTES);  // dummy zero row
    g_cnt[(path * N_BATCH + n) * T_SEQ + seq] = cnt;
}

// ---------------------------------------------------------------------------
// K1a: sparse GEMM1. grid (hb, n, path), 512 threads = 16 warps.
// Warp handles t = wrp, wrp+16, ... Lane owns 4 hidden units.
// ---------------------------------------------------------------------------
__global__ void __launch_bounds__(512) k_gemm1(const float* __restrict__ w_main,
                                               const float* __restrict__ w_loc) {
    extern __shared__ float ws[];   // [157][128]; row 156 = zeros
    int hb = blockIdx.x, n = blockIdx.y, path = blockIdx.z;
    int tid = threadIdx.x;
    const float* wa = path ? w_loc : w_main;

    for (int i = tid; i < HB_SZ * C_IN; i += 512) {
        int hl = i / C_IN, c = i % C_IN;
        ws[c * HB_SZ + hl] = wa[(size_t)(hb * HB_SZ + hl) * C_IN + c];
    }
    for (int i = tid; i < HB_SZ; i += 512) ws[C_IN * HB_SZ + i] = 0.0f;
    __syncthreads();

    uint32_t ws32;
    asm("{ .reg .u64 t; cvta.to.shared.u64 t, %1; cvt.u32.u64 %0, t; }"
        : "=r"(ws32) : "l"(ws));

    int wrp = tid >> 5, lane = tid & 31;
    uint32_t base = ws32 + lane * 16;
    float* pp = g_pre + (size_t)((path * N_BATCH + n) * HB_CNT + hb) * (T_SEQ * HB_SZ);
    const int seqbase = (path * N_BATCH + n) * T_SEQ;

    for (int t = wrp; t < T_SEQ; t += 16) {
        const unsigned* ib = g_idx + (size_t)(seqbase + t) * IDX_CAP;
        int cnt = g_cnt[seqbase + t];
        unsigned long long acc0 = 0ULL, acc1 = 0ULL;
        for (int k = 0; k < cnt; k += 4) {
            uint4 v = *(const uint4*)(ib + k);
            unsigned long long a, b;
            asm volatile("ld.shared.v2.b64 {%0,%1}, [%2];" : "=l"(a), "=l"(b) : "r"(base + v.x));
            asm("add.rn.f32x2 %0, %0, %1;" : "+l"(acc0) : "l"(a));
            asm("add.rn.f32x2 %0, %0, %1;" : "+l"(acc1) : "l"(b));
            asm volatile("ld.shared.v2.b64 {%0,%1}, [%2];" : "=l"(a), "=l"(b) : "r"(base + v.y));
            asm("add.rn.f32x2 %0, %0, %1;" : "+l"(acc0) : "l"(a));
            asm("add.rn.f32x2 %0, %0, %1;" : "+l"(acc1) : "l"(b));
            asm volatile("ld.shared.v2.b64 {%0,%1}, [%2];" : "=l"(a), "=l"(b) : "r"(base + v.z));
            asm("add.rn.f32x2 %0, %0, %1;" : "+l"(acc0) : "l"(a));
            asm("add.rn.f32x2 %0, %0, %1;" : "+l"(acc1) : "l"(b));
            asm volatile("ld.shared.v2.b64 {%0,%1}, [%2];" : "=l"(a), "=l"(b) : "r"(base + v.w));
            asm("add.rn.f32x2 %0, %0, %1;" : "+l"(acc0) : "l"(a));
            asm("add.rn.f32x2 %0, %0, %1;" : "+l"(acc1) : "l"(b));
        }
        uint2 u0 = *reinterpret_cast<uint2*>(&acc0);
        uint2 u1 = *reinterpret_cast<uint2*>(&acc1);
        float4 r;
        r.x = __uint_as_float(u0.x); r.y = __uint_as_float(u0.y);
        r.z = __uint_as_float(u1.x); r.w = __uint_as_float(u1.y);
        *(float4*)(pp + t * HB_SZ + lane * 4) = r;
    }
}

// ---------------------------------------------------------------------------
// K1b: layer-1 recurrence + vectorized sparse L2 partial.
// grid (hb, n, path), 128 threads.
// ---------------------------------------------------------------------------
__global__ void __launch_bounds__(HB_SZ) k_neuron1(const float* __restrict__ wb_main,
                                                   const float* __restrict__ wb_loc) {
    __shared__ float w2s[HB_SZ * O_DIM];      // [h][o], rows 80B
    __shared__ unsigned sb[T_SEQ * 4];        // spike bitmasks per t (4 warps)

    int hb = blockIdx.x, n = blockIdx.y, path = blockIdx.z;
    int tid = threadIdx.x;
    int lane = tid & 31, wrp = tid >> 5;
    const float* wb = path ? wb_loc : wb_main;

    for (int i = tid; i < O_DIM * HB_SZ; i += HB_SZ) {
        int h = i % HB_SZ, o = i / HB_SZ;
        w2s[h * O_DIM + o] = wb[(size_t)o * H_DIM + hb * HB_SZ + h];
    }
    __syncthreads();

    const float* pp = g_pre + (size_t)((path * N_BATCH + n) * HB_CNT + hb) * (T_SEQ * HB_SZ);

    float A = 0.f, B = 0.f, P = 0.f, Q = 0.f;
    unsigned hist = 0u;
    #pragma unroll 4
    for (int t = 0; t < T_SEQ; t++) {
        float acc = pp[t * HB_SZ + tid];
        B = LAM_S * (B + A);
        A = LAM_S * A + acc;
        float u  = K_PSP * B;
        float um = u + C_REF * Q;
        unsigned spk = (um >= THETA) ? 1u : 0u;
        float s = (float)spk;
        float aged = (float)((hist >> 14) & 1u);
        Q = LAM_R * (Q + P + s) - aged * C_Q16;
        P = LAM_R * (P + s)     - aged * C_P16;
        hist = (hist << 1) | spk;
        unsigned bal = __ballot_sync(0xffffffffu, spk);
        if (lane == 0) sb[t * 4 + wrp] = bal;
    }
    __syncthreads();

    // L2 partial: one t per thread, 20 packed accumulators, LDS.128 rows.
    uint32_t w2s32;
    asm("{ .reg .u64 t; cvta.to.shared.u64 t, %1; cvt.u32.u64 %0, t; }"
        : "=r"(w2s32) : "l"(w2s));

    float* vout = g_v2part + (size_t)((path * HB_CNT + hb) * N_BATCH + n) * (T_SEQ * O_DIM);
    for (int t = tid; t < T_SEQ; t += HB_SZ) {
        unsigned long long acc[10];
        #pragma unroll
        for (int i = 0; i < 10; i++) acc[i] = 0ULL;
        #pragma unroll
        for (int wd = 0; wd < 4; wd++) {
            unsigned m = sb[t * 4 + wd];
            while (m) {
                int j = __ffs(m) - 1;
                m &= m - 1u;
                uint32_t row = w2s32 + (unsigned)((wd * 32 + j) * (O_DIM * 4));
                unsigned long long a, b;
                asm volatile("ld.shared.v2.b64 {%0,%1}, [%2];" : "=l"(a), "=l"(b) : "r"(row));
                asm("add.rn.f32x2 %0, %0, %1;" : "+l"(acc[0]) : "l"(a));
                asm("add.rn.f32x2 %0, %0, %1;" : "+l"(acc[1]) : "l"(b));
                asm volatile("ld.shared.v2.b64 {%0,%1}, [%2];" : "=l"(a), "=l"(b) : "r"(row + 16));
                asm("add.rn.f32x2 %0, %0, %1;" : "+l"(acc[2]) : "l"(a));
                asm("add.rn.f32x2 %0, %0, %1;" : "+l"(acc[3]) : "l"(b));
                asm volatile("ld.shared.v2.b64 {%0,%1}, [%2];" : "=l"(a), "=l"(b) : "r"(row + 32));
                asm("add.rn.f32x2 %0, %0, %1;" : "+l"(acc[4]) : "l"(a));
                asm("add.rn.f32x2 %0, %0, %1;" : "+l"(acc[5]) : "l"(b));
                asm volatile("ld.shared.v2.b64 {%0,%1}, [%2];" : "=l"(a), "=l"(b) : "r"(row + 48));
                asm("add.rn.f32x2 %0, %0, %1;" : "+l"(acc[6]) : "l"(a));
                asm("add.rn.f32x2 %0, %0, %1;" : "+l"(acc[7]) : "l"(b));
                asm volatile("ld.shared.v2.b64 {%0,%1}, [%2];" : "=l"(a), "=l"(b) : "r"(row + 64));
                asm("add.rn.f32x2 %0, %0, %1;" : "+l"(acc[8]) : "l"(a));
                asm("add.rn.f32x2 %0, %0, %1;" : "+l"(acc[9]) : "l"(b));
            }
        }
        float2* vp = (float2*)(vout + t * O_DIM);
        #pragma unroll
        for (int i = 0; i < 10; i++) vp[i] = *reinterpret_cast<float2*>(&acc[i]);
    }
}

// ---------------------------------------------------------------------------
// K2: sum 8 h-block partials into smem, then layer-2 recurrence + output.
// grid 256 = (path, n), 128 threads.
// ---------------------------------------------------------------------------
#define TO (T_SEQ * O_DIM)   // 3120
__global__ void __launch_bounds__(128) k_final(float* __restrict__ out) {
    __shared__ float v[TO];
    int b = blockIdx.x;
    int path = b >> 7, n = b & 127;
    int tid = threadIdx.x;

    const float* basep = g_v2part + (size_t)(path * HB_CNT * N_BATCH + n) * TO;
    for (int i = tid; i < TO; i += 128) {
        float acc = 0.f;
        #pragma unroll
        for (int hb = 0; hb < HB_CNT; hb++)
            acc += basep[(size_t)hb * N_BATCH * TO + i];
        v[i] = acc;
    }
    __syncthreads();

    if (tid < O_DIM) {
        int o = tid;
        float* op = out + ((size_t)n * O_DIM + o) * 312 + path * T_SEQ;
        float A = 0.f, B = 0.f, P = 0.f, Q = 0.f;
        unsigned hist = 0u;
        #pragma unroll 4
        for (int t = 0; t < T_SEQ; t++) {
            float pre = v[t * O_DIM + o];
            B = LAM_S * (B + A);
            A = LAM_S * A + pre;
            float u  = K_PSP * B;
            float um = u + C_REF * Q;
            unsigned spk = (um >= THETA) ? 1u : 0u;
            float s = (float)spk;
            float aged = (float)((hist >> 14) & 1u);
            Q = LAM_R * (Q + P + s) - aged * C_Q16;
            P = LAM_R * (P + s)     - aged * C_P16;
            hist = (hist << 1) | spk;
            op[t] = s;
        }
    }
}

// ---------------------------------------------------------------------------
extern "C" void kernel_launch(void* const* d_in, const int* in_sizes, int n_in,
                              void* d_out, int out_size) {
    const float* x   = (const float*)d_in[0];
    const float* w1  = (const float*)d_in[1];
    const float* w2  = (const float*)d_in[2];
    const float* wl1 = (const float*)d_in[3];
    const float* wl2 = (const float*)d_in[4];
    float* out = (float*)d_out;

    const int SM0 = C_IN * T_SEQ * 4;          // 97344
    const int SM1 = 157 * HB_SZ * 4;           // 80384
    cudaFuncSetAttribute(k_bitify, cudaFuncAttributeMaxDynamicSharedMemorySize, SM0);
    cudaFuncSetAttribute(k_gemm1,  cudaFuncAttributeMaxDynamicSharedMemorySize, SM1);

    k_bitify<<<N_BATCH, 320, SM0>>>(x);

    dim3 g1(HB_CNT, N_BATCH, 2);
    k_gemm1<<<g1, 512, SM1>>>(w1, wl1);
    k_neuron1<<<g1, HB_SZ>>>(w2, wl2);

    k_final<<<2 * N_BATCH, 128>>>(out);
}